// round 1
// baseline (speedup 1.0000x reference)
#include <cuda_runtime.h>
#include <math.h>

#define MAXN 100000
#define MAXE 800000
#define HID 256
#define BN_EPS 1e-5f

// ---------------- scratch (device globals; no allocation allowed) ----------
__device__ float g_h[(size_t)MAXN * HID];      // h = x @ W
__device__ float g_agg[(size_t)MAXN * HID];    // scatter accumulator -> v
__device__ float g_x1[(size_t)MAXN * HID];     // layer-1 output (layer-2 input)
__device__ float g_deg[MAXN];
__device__ float g_dinv[MAXN];
__device__ float g_invdeg[MAXN];
__device__ float g_stats[2 * HID];             // per-channel sum, sumsq
__device__ float g_scale[HID];
__device__ float g_shift[HID];

// ---------------- degree kernels ----------------
__global__ void k_init_deg(int n) {
    int i = blockIdx.x * blockDim.x + threadIdx.x;
    if (i < n) g_deg[i] = 1.0f;
}

__global__ void k_count(const int* __restrict__ dst, int e) {
    int i = blockIdx.x * blockDim.x + threadIdx.x;
    if (i < e) atomicAdd(&g_deg[dst[i]], 1.0f);
}

__global__ void k_dinv(int n) {
    int i = blockIdx.x * blockDim.x + threadIdx.x;
    if (i < n) {
        float d = g_deg[i];
        g_dinv[i] = rsqrtf(d);
        g_invdeg[i] = 1.0f / d;
    }
}

// ---------------- SGEMM: C[M,HID] = A[M,K] @ B[K,HID] ----------------
// 128x128 tile, BK=8, 256 threads, 8x8 per-thread microtile.
__global__ void __launch_bounds__(256) k_sgemm(
    const float* __restrict__ A, const float* __restrict__ B,
    float* __restrict__ C, int M, int K)
{
    __shared__ float As[8][128];
    __shared__ float Bs[8][128];
    const int tid  = threadIdx.x;
    const int brow = blockIdx.y;
    const int bcol = blockIdx.x;

    const int aRow = tid >> 1;            // 0..127
    const int aCol = (tid & 1) * 4;       // 0 or 4
    const int bRow = tid >> 5;            // 0..7
    const int bCol = (tid & 31) * 4;      // 0..124

    const int tx = tid & 15;
    const int ty = tid >> 4;

    const int gRowA = brow * 128 + aRow;

    float acc[8][8];
    #pragma unroll
    for (int i = 0; i < 8; i++)
        #pragma unroll
        for (int j = 0; j < 8; j++) acc[i][j] = 0.0f;

    for (int k0 = 0; k0 < K; k0 += 8) {
        float4 a4 = make_float4(0.f, 0.f, 0.f, 0.f);
        if (gRowA < M)
            a4 = *(const float4*)(A + (size_t)gRowA * K + k0 + aCol);
        As[aCol + 0][aRow] = a4.x;
        As[aCol + 1][aRow] = a4.y;
        As[aCol + 2][aRow] = a4.z;
        As[aCol + 3][aRow] = a4.w;

        *(float4*)&Bs[bRow][bCol] =
            *(const float4*)(B + (size_t)(k0 + bRow) * HID + bcol * 128 + bCol);

        __syncthreads();

        #pragma unroll
        for (int k = 0; k < 8; k++) {
            float ra[8], rb[8];
            #pragma unroll
            for (int i = 0; i < 8; i++) ra[i] = As[k][ty * 8 + i];
            #pragma unroll
            for (int j = 0; j < 8; j++) rb[j] = Bs[k][tx * 8 + j];
            #pragma unroll
            for (int i = 0; i < 8; i++)
                #pragma unroll
                for (int j = 0; j < 8; j++)
                    acc[i][j] = fmaf(ra[i], rb[j], acc[i][j]);
        }
        __syncthreads();
    }

    #pragma unroll
    for (int i = 0; i < 8; i++) {
        int r = brow * 128 + ty * 8 + i;
        if (r < M) {
            float* cp = C + (size_t)r * HID + bcol * 128 + tx * 8;
            *(float4*)(cp)     = make_float4(acc[i][0], acc[i][1], acc[i][2], acc[i][3]);
            *(float4*)(cp + 4) = make_float4(acc[i][4], acc[i][5], acc[i][6], acc[i][7]);
        }
    }
}

// ---------------- scatter-aggregate: warp per edge ----------------
__global__ void k_scatter(const int* __restrict__ src, const int* __restrict__ dst, int e) {
    int t = blockIdx.x * blockDim.x + threadIdx.x;
    int w = t >> 5;
    int lane = t & 31;
    if (w >= e) return;
    int s = src[w];
    int d = dst[w];
    float c = g_dinv[s] * g_dinv[d];
    const float4* hp = (const float4*)(g_h + (size_t)s * HID);
    float* ap = g_agg + (size_t)d * HID + lane * 4;
    float4 v0 = hp[lane];        // channels [0,128)
    float4 v1 = hp[lane + 32];   // channels [128,256)
    atomicAdd(ap + 0,   v0.x * c);
    atomicAdd(ap + 1,   v0.y * c);
    atomicAdd(ap + 2,   v0.z * c);
    atomicAdd(ap + 3,   v0.w * c);
    atomicAdd(ap + 128, v1.x * c);
    atomicAdd(ap + 129, v1.y * c);
    atomicAdd(ap + 130, v1.z * c);
    atomicAdd(ap + 131, v1.w * c);
}

// ---------------- finalize v = agg + h*invdeg + b; accumulate BN stats ----
__global__ void __launch_bounds__(HID) k_finalize_stats(const float* __restrict__ bias, int n) {
    const int c  = threadIdx.x;        // channel
    const int r0 = blockIdx.x * 128;
    const float b = bias[c];
    float s = 0.f, s2 = 0.f;
    int rmax = n - r0; if (rmax > 128) rmax = 128;
    #pragma unroll 4
    for (int i = 0; i < rmax; i++) {
        int r = r0 + i;
        size_t idx = (size_t)r * HID + c;
        float v = g_agg[idx] + g_h[idx] * g_invdeg[r] + b;
        g_agg[idx] = v;
        s  += v;
        s2 += v * v;
    }
    atomicAdd(&g_stats[c], s);
    atomicAdd(&g_stats[HID + c], s2);
}

// ---------------- fold stats -> scale/shift ----------------
__global__ void k_bn_params(const float* __restrict__ gamma,
                            const float* __restrict__ beta, int n) {
    int c = threadIdx.x;
    float invn = 1.0f / (float)n;
    float mu  = g_stats[c] * invn;
    float var = g_stats[HID + c] * invn - mu * mu;
    var = fmaxf(var, 0.0f);
    float inv = rsqrtf(var + BN_EPS);
    float sc = gamma[c] * inv;
    g_scale[c] = sc;
    g_shift[c] = beta[c] - mu * sc;
}

// ---------------- apply BN + ReLU ----------------
__global__ void k_apply(float* __restrict__ out, int n) {
    int i = blockIdx.x * blockDim.x + threadIdx.x;
    if (i < n * HID) {
        int c = i & (HID - 1);
        out[i] = fmaxf(fmaf(g_agg[i], g_scale[c], g_shift[c]), 0.0f);
    }
}

// ---------------- launch ----------------
extern "C" void kernel_launch(void* const* d_in, const int* in_sizes, int n_in,
                              void* d_out, int out_size) {
    const float* x   = (const float*)d_in[0];
    const int*   ei  = (const int*)  d_in[1];
    const float* W1  = (const float*)d_in[2];
    const float* b1  = (const float*)d_in[3];
    const float* g1  = (const float*)d_in[4];
    const float* be1 = (const float*)d_in[5];
    const float* W2  = (const float*)d_in[6];
    const float* b2  = (const float*)d_in[7];
    const float* g2  = (const float*)d_in[8];
    const float* be2 = (const float*)d_in[9];

    int n = in_sizes[0] / 384;
    int e = in_sizes[1] / 2;
    const int* src = ei;
    const int* dst = ei + e;

    void *p_h = nullptr, *p_agg = nullptr, *p_x1 = nullptr, *p_stats = nullptr;
    cudaGetSymbolAddress(&p_h,     g_h);
    cudaGetSymbolAddress(&p_agg,   g_agg);
    cudaGetSymbolAddress(&p_x1,    g_x1);
    cudaGetSymbolAddress(&p_stats, g_stats);

    const int T = 256;
    dim3 ggrid(HID / 128, (n + 127) / 128);
    long ethreads = (long)e * 32;
    int sgrid = (int)((ethreads + T - 1) / T);
    int fgrid = (n + 127) / 128;
    int agrid = (int)(((long)n * HID + T - 1) / T);

    // degrees (shared by both layers)
    k_init_deg<<<(n + T - 1) / T, T>>>(n);
    k_count<<<(e + T - 1) / T, T>>>(dst, e);
    k_dinv<<<(n + T - 1) / T, T>>>(n);

    // ---- layer 1 ----
    cudaMemsetAsync(p_agg, 0, (size_t)n * HID * sizeof(float));
    cudaMemsetAsync(p_stats, 0, 2 * HID * sizeof(float));
    k_sgemm<<<ggrid, 256>>>(x, W1, (float*)p_h, n, 384);
    k_scatter<<<sgrid, T>>>(src, dst, e);
    k_finalize_stats<<<fgrid, HID>>>(b1, n);
    k_bn_params<<<1, HID>>>(g1, be1, n);
    k_apply<<<agrid, T>>>((float*)p_x1, n);

    // ---- layer 2 ----
    cudaMemsetAsync(p_agg, 0, (size_t)n * HID * sizeof(float));
    cudaMemsetAsync(p_stats, 0, 2 * HID * sizeof(float));
    k_sgemm<<<ggrid, 256>>>((const float*)p_x1, W2, (float*)p_h, n, 256);
    k_scatter<<<sgrid, T>>>(src, dst, e);
    k_finalize_stats<<<fgrid, HID>>>(b2, n);
    k_bn_params<<<1, HID>>>(g2, be2, n);
    k_apply<<<agrid, T>>>((float*)d_out, n);
}

// round 2
// speedup vs baseline: 1.6628x; 1.6628x over previous
#include <cuda_runtime.h>
#include <math.h>

#define MAXN 100000
#define MAXE 800000
#define HID 256
#define BN_EPS 1e-5f

// ---------------- scratch (device globals) ----------------
__device__ float g_h[(size_t)MAXN * HID];      // h = x @ W
__device__ float g_v[(size_t)MAXN * HID];      // gathered pre-BN activations
__device__ float g_x1[(size_t)MAXN * HID];     // layer-1 output
__device__ float g_dinv[MAXN];
__device__ float g_invdeg[MAXN];
__device__ int   g_cnt[MAXN];                  // in-degree counts
__device__ int   g_cur[MAXN];                  // fill cursors
__device__ int   g_row[MAXN + 1];              // CSR row pointers
__device__ int   g_adj[MAXE];                  // CSR adjacency (src ids)
__device__ float g_stats[2 * HID];             // per-channel sum, sumsq
__device__ float g_scale[HID];
__device__ float g_shift[HID];

// ---------------- CSR build ----------------
__global__ void k_count(const int* __restrict__ dst, int e) {
    int i = blockIdx.x * blockDim.x + threadIdx.x;
    if (i < e) atomicAdd(&g_cnt[dst[i]], 1);
}

__global__ void k_dinv(int n) {
    int i = blockIdx.x * blockDim.x + threadIdx.x;
    if (i < n) {
        float d = (float)g_cnt[i] + 1.0f;
        g_dinv[i] = rsqrtf(d);
        g_invdeg[i] = 1.0f / d;
    }
}

// single-block chunked exclusive scan of g_cnt -> g_row
__global__ void __launch_bounds__(1024) k_scan(int n) {
    __shared__ int sh[1024];
    const int t = threadIdx.x;
    const int chunk = (n + 1023) >> 10;
    int lo = t * chunk;
    int hi = lo + chunk; if (hi > n) hi = n; if (lo > n) lo = n;
    int s = 0;
    for (int i = lo; i < hi; i++) s += g_cnt[i];
    sh[t] = s;
    __syncthreads();
    // Hillis-Steele inclusive scan
    for (int off = 1; off < 1024; off <<= 1) {
        int v = (t >= off) ? sh[t - off] : 0;
        __syncthreads();
        sh[t] += v;
        __syncthreads();
    }
    int run = (t == 0) ? 0 : sh[t - 1];
    for (int i = lo; i < hi; i++) {
        g_row[i] = run;
        run += g_cnt[i];
    }
    if (hi == n) g_row[n] = run;
}

__global__ void k_fill(const int* __restrict__ src, const int* __restrict__ dst, int e) {
    int i = blockIdx.x * blockDim.x + threadIdx.x;
    if (i < e) {
        int d = dst[i];
        int p = atomicAdd(&g_cur[d], 1);
        g_adj[g_row[d] + p] = src[i];
    }
}

// ---------------- SGEMM: C[M,HID] = A[M,K] @ B[K,HID] ----------------
__global__ void __launch_bounds__(256) k_sgemm(
    const float* __restrict__ A, const float* __restrict__ B,
    float* __restrict__ C, int M, int K)
{
    __shared__ float As[8][128];
    __shared__ float Bs[8][128];
    const int tid  = threadIdx.x;
    const int brow = blockIdx.y;
    const int bcol = blockIdx.x;

    const int aRow = tid >> 1;
    const int aCol = (tid & 1) * 4;
    const int bRow = tid >> 5;
    const int bCol = (tid & 31) * 4;

    const int tx = tid & 15;
    const int ty = tid >> 4;

    const int gRowA = brow * 128 + aRow;

    float acc[8][8];
    #pragma unroll
    for (int i = 0; i < 8; i++)
        #pragma unroll
        for (int j = 0; j < 8; j++) acc[i][j] = 0.0f;

    for (int k0 = 0; k0 < K; k0 += 8) {
        float4 a4 = make_float4(0.f, 0.f, 0.f, 0.f);
        if (gRowA < M)
            a4 = *(const float4*)(A + (size_t)gRowA * K + k0 + aCol);
        As[aCol + 0][aRow] = a4.x;
        As[aCol + 1][aRow] = a4.y;
        As[aCol + 2][aRow] = a4.z;
        As[aCol + 3][aRow] = a4.w;

        *(float4*)&Bs[bRow][bCol] =
            *(const float4*)(B + (size_t)(k0 + bRow) * HID + bcol * 128 + bCol);

        __syncthreads();

        #pragma unroll
        for (int k = 0; k < 8; k++) {
            float ra[8], rb[8];
            #pragma unroll
            for (int i = 0; i < 8; i++) ra[i] = As[k][ty * 8 + i];
            #pragma unroll
            for (int j = 0; j < 8; j++) rb[j] = Bs[k][tx * 8 + j];
            #pragma unroll
            for (int i = 0; i < 8; i++)
                #pragma unroll
                for (int j = 0; j < 8; j++)
                    acc[i][j] = fmaf(ra[i], rb[j], acc[i][j]);
        }
        __syncthreads();
    }

    #pragma unroll
    for (int i = 0; i < 8; i++) {
        int r = brow * 128 + ty * 8 + i;
        if (r < M) {
            float* cp = C + (size_t)r * HID + bcol * 128 + tx * 8;
            *(float4*)(cp)     = make_float4(acc[i][0], acc[i][1], acc[i][2], acc[i][3]);
            *(float4*)(cp + 4) = make_float4(acc[i][4], acc[i][5], acc[i][6], acc[i][7]);
        }
    }
}

// ---------------- fused CSR gather + self-loop + bias + BN stats ----------
// warp per node; lane owns channels [lane*4, lane*4+4) and +128.
__global__ void __launch_bounds__(256) k_gather(const float* __restrict__ bias, int n) {
    __shared__ float sh_sum[HID];
    __shared__ float sh_sq[HID];
    const int tid  = threadIdx.x;
    const int lane = tid & 31;
    const int warp = tid >> 5;

    for (int c = tid; c < HID; c += 256) { sh_sum[c] = 0.f; sh_sq[c] = 0.f; }
    __syncthreads();

    const float4 b0 = *(const float4*)(bias + lane * 4);
    const float4 b1 = *(const float4*)(bias + 128 + lane * 4);

    float4 ts0 = make_float4(0,0,0,0), ts1 = make_float4(0,0,0,0);   // sum
    float4 tq0 = make_float4(0,0,0,0), tq1 = make_float4(0,0,0,0);   // sumsq

    for (int node = blockIdx.x * 8 + warp; node < n; node += gridDim.x * 8) {
        const int start = g_row[node];
        const int end   = g_row[node + 1];
        const float dd  = g_dinv[node];

        float4 a0 = make_float4(0,0,0,0), a1 = make_float4(0,0,0,0);

        int j = start;
        for (; j + 1 < end; j += 2) {
            int s0 = g_adj[j];
            int s1 = g_adj[j + 1];
            float c0 = g_dinv[s0] * dd;
            float c1 = g_dinv[s1] * dd;
            const float4* p0 = (const float4*)(g_h + (size_t)s0 * HID);
            const float4* p1 = (const float4*)(g_h + (size_t)s1 * HID);
            float4 u0 = p0[lane], u1 = p0[lane + 32];
            float4 w0 = p1[lane], w1 = p1[lane + 32];
            a0.x = fmaf(u0.x, c0, a0.x); a0.y = fmaf(u0.y, c0, a0.y);
            a0.z = fmaf(u0.z, c0, a0.z); a0.w = fmaf(u0.w, c0, a0.w);
            a1.x = fmaf(u1.x, c0, a1.x); a1.y = fmaf(u1.y, c0, a1.y);
            a1.z = fmaf(u1.z, c0, a1.z); a1.w = fmaf(u1.w, c0, a1.w);
            a0.x = fmaf(w0.x, c1, a0.x); a0.y = fmaf(w0.y, c1, a0.y);
            a0.z = fmaf(w0.z, c1, a0.z); a0.w = fmaf(w0.w, c1, a0.w);
            a1.x = fmaf(w1.x, c1, a1.x); a1.y = fmaf(w1.y, c1, a1.y);
            a1.z = fmaf(w1.z, c1, a1.z); a1.w = fmaf(w1.w, c1, a1.w);
        }
        if (j < end) {
            int s0 = g_adj[j];
            float c0 = g_dinv[s0] * dd;
            const float4* p0 = (const float4*)(g_h + (size_t)s0 * HID);
            float4 u0 = p0[lane], u1 = p0[lane + 32];
            a0.x = fmaf(u0.x, c0, a0.x); a0.y = fmaf(u0.y, c0, a0.y);
            a0.z = fmaf(u0.z, c0, a0.z); a0.w = fmaf(u0.w, c0, a0.w);
            a1.x = fmaf(u1.x, c0, a1.x); a1.y = fmaf(u1.y, c0, a1.y);
            a1.z = fmaf(u1.z, c0, a1.z); a1.w = fmaf(u1.w, c0, a1.w);
        }

        // self-loop + bias
        const float id = g_invdeg[node];
        const float4* hp = (const float4*)(g_h + (size_t)node * HID);
        float4 h0 = hp[lane], h1 = hp[lane + 32];
        a0.x = fmaf(h0.x, id, a0.x) + b0.x; a0.y = fmaf(h0.y, id, a0.y) + b0.y;
        a0.z = fmaf(h0.z, id, a0.z) + b0.z; a0.w = fmaf(h0.w, id, a0.w) + b0.w;
        a1.x = fmaf(h1.x, id, a1.x) + b1.x; a1.y = fmaf(h1.y, id, a1.y) + b1.y;
        a1.z = fmaf(h1.z, id, a1.z) + b1.z; a1.w = fmaf(h1.w, id, a1.w) + b1.w;

        float4* vp = (float4*)(g_v + (size_t)node * HID);
        vp[lane] = a0;
        vp[lane + 32] = a1;

        ts0.x += a0.x; ts0.y += a0.y; ts0.z += a0.z; ts0.w += a0.w;
        ts1.x += a1.x; ts1.y += a1.y; ts1.z += a1.z; ts1.w += a1.w;
        tq0.x = fmaf(a0.x, a0.x, tq0.x); tq0.y = fmaf(a0.y, a0.y, tq0.y);
        tq0.z = fmaf(a0.z, a0.z, tq0.z); tq0.w = fmaf(a0.w, a0.w, tq0.w);
        tq1.x = fmaf(a1.x, a1.x, tq1.x); tq1.y = fmaf(a1.y, a1.y, tq1.y);
        tq1.z = fmaf(a1.z, a1.z, tq1.z); tq1.w = fmaf(a1.w, a1.w, tq1.w);
    }

    // reduce stats: per-lane channels into shared (cross-warp via shared atomics)
    const int c0 = lane * 4;
    atomicAdd(&sh_sum[c0 + 0], ts0.x); atomicAdd(&sh_sum[c0 + 1], ts0.y);
    atomicAdd(&sh_sum[c0 + 2], ts0.z); atomicAdd(&sh_sum[c0 + 3], ts0.w);
    atomicAdd(&sh_sum[c0 + 128], ts1.x); atomicAdd(&sh_sum[c0 + 129], ts1.y);
    atomicAdd(&sh_sum[c0 + 130], ts1.z); atomicAdd(&sh_sum[c0 + 131], ts1.w);
    atomicAdd(&sh_sq[c0 + 0], tq0.x); atomicAdd(&sh_sq[c0 + 1], tq0.y);
    atomicAdd(&sh_sq[c0 + 2], tq0.z); atomicAdd(&sh_sq[c0 + 3], tq0.w);
    atomicAdd(&sh_sq[c0 + 128], tq1.x); atomicAdd(&sh_sq[c0 + 129], tq1.y);
    atomicAdd(&sh_sq[c0 + 130], tq1.z); atomicAdd(&sh_sq[c0 + 131], tq1.w);
    __syncthreads();

    if (tid < HID) {
        atomicAdd(&g_stats[tid], sh_sum[tid]);
        atomicAdd(&g_stats[HID + tid], sh_sq[tid]);
    }
}

// ---------------- fold stats -> scale/shift ----------------
__global__ void k_bn_params(const float* __restrict__ gamma,
                            const float* __restrict__ beta, int n) {
    int c = threadIdx.x;
    float invn = 1.0f / (float)n;
    float mu  = g_stats[c] * invn;
    float var = g_stats[HID + c] * invn - mu * mu;
    var = fmaxf(var, 0.0f);
    float inv = rsqrtf(var + BN_EPS);
    float sc = gamma[c] * inv;
    g_scale[c] = sc;
    g_shift[c] = beta[c] - mu * sc;
}

// ---------------- apply BN + ReLU ----------------
__global__ void k_apply(float* __restrict__ out, int n) {
    int i = blockIdx.x * blockDim.x + threadIdx.x;
    if (i < n * HID) {
        int c = i & (HID - 1);
        out[i] = fmaxf(fmaf(g_v[i], g_scale[c], g_shift[c]), 0.0f);
    }
}

// ---------------- launch ----------------
extern "C" void kernel_launch(void* const* d_in, const int* in_sizes, int n_in,
                              void* d_out, int out_size) {
    const float* x   = (const float*)d_in[0];
    const int*   ei  = (const int*)  d_in[1];
    const float* W1  = (const float*)d_in[2];
    const float* b1  = (const float*)d_in[3];
    const float* g1  = (const float*)d_in[4];
    const float* be1 = (const float*)d_in[5];
    const float* W2  = (const float*)d_in[6];
    const float* b2  = (const float*)d_in[7];
    const float* g2  = (const float*)d_in[8];
    const float* be2 = (const float*)d_in[9];

    int n = in_sizes[0] / 384;
    int e = in_sizes[1] / 2;
    const int* src = ei;
    const int* dst = ei + e;

    void *p_h = nullptr, *p_x1 = nullptr, *p_stats = nullptr;
    void *p_cnt = nullptr, *p_cur = nullptr;
    cudaGetSymbolAddress(&p_h,     g_h);
    cudaGetSymbolAddress(&p_x1,    g_x1);
    cudaGetSymbolAddress(&p_stats, g_stats);
    cudaGetSymbolAddress(&p_cnt,   g_cnt);
    cudaGetSymbolAddress(&p_cur,   g_cur);

    const int T = 256;
    dim3 ggrid(HID / 128, (n + 127) / 128);
    const int gat_grid = 1184;               // 8 blocks/SM-ish
    int agrid = (int)(((long)n * HID + T - 1) / T);

    // ---- CSR build (shared by both layers) ----
    cudaMemsetAsync(p_cnt, 0, (size_t)n * sizeof(int));
    cudaMemsetAsync(p_cur, 0, (size_t)n * sizeof(int));
    k_count<<<(e + T - 1) / T, T>>>(dst, e);
    k_dinv<<<(n + T - 1) / T, T>>>(n);
    k_scan<<<1, 1024>>>(n);
    k_fill<<<(e + T - 1) / T, T>>>(src, dst, e);

    // ---- layer 1 ----
    cudaMemsetAsync(p_stats, 0, 2 * HID * sizeof(float));
    k_sgemm<<<ggrid, 256>>>(x, W1, (float*)p_h, n, 384);
    k_gather<<<gat_grid, 256>>>(b1, n);
    k_bn_params<<<1, HID>>>(g1, be1, n);
    k_apply<<<agrid, T>>>((float*)p_x1, n);

    // ---- layer 2 ----
    cudaMemsetAsync(p_stats, 0, 2 * HID * sizeof(float));
    k_sgemm<<<ggrid, 256>>>((const float*)p_x1, W2, (float*)p_h, n, 256);
    k_gather<<<gat_grid, 256>>>(b2, n);
    k_bn_params<<<1, HID>>>(g2, be2, n);
    k_apply<<<agrid, T>>>((float*)d_out, n);
}

// round 3
// speedup vs baseline: 1.9958x; 1.2003x over previous
#include <cuda_runtime.h>
#include <cuda_bf16.h>
#include <math.h>

#define MAXN 100000
#define MAXE 800000
#define HID 256
#define BN_EPS 1e-5f

// ---------------- scratch (device globals) ----------------
__device__ float g_h[(size_t)MAXN * HID];      // GEMM output
__device__ float g_v[(size_t)MAXN * HID];      // gathered pre-BN activations
__device__ float g_dinv[MAXN];
__device__ float g_invdeg[MAXN];
__device__ int   g_cnt[MAXN];
__device__ int   g_cur[MAXN];
__device__ int   g_row[MAXN + 1];
__device__ int   g_adj[MAXE];
__device__ float g_stats[2 * HID];
__device__ float g_scale[HID];
__device__ float g_shift[HID];

// ---------------- CSR build ----------------
__global__ void k_count(const int* __restrict__ dst, int e) {
    int i = blockIdx.x * blockDim.x + threadIdx.x;
    if (i < e) atomicAdd(&g_cnt[dst[i]], 1);
}

__global__ void k_dinv(int n) {
    int i = blockIdx.x * blockDim.x + threadIdx.x;
    if (i < n) {
        float d = (float)g_cnt[i] + 1.0f;
        g_dinv[i] = rsqrtf(d);
        g_invdeg[i] = 1.0f / d;
    }
}

__global__ void __launch_bounds__(1024) k_scan(int n) {
    __shared__ int sh[1024];
    const int t = threadIdx.x;
    const int chunk = (n + 1023) >> 10;
    int lo = t * chunk;
    int hi = lo + chunk; if (hi > n) hi = n; if (lo > n) lo = n;
    int s = 0;
    for (int i = lo; i < hi; i++) s += g_cnt[i];
    sh[t] = s;
    __syncthreads();
    for (int off = 1; off < 1024; off <<= 1) {
        int v = (t >= off) ? sh[t - off] : 0;
        __syncthreads();
        sh[t] += v;
        __syncthreads();
    }
    int run = (t == 0) ? 0 : sh[t - 1];
    for (int i = lo; i < hi; i++) {
        g_row[i] = run;
        run += g_cnt[i];
    }
    if (hi == n) g_row[n] = run;
}

__global__ void k_fill(const int* __restrict__ src, const int* __restrict__ dst, int e) {
    int i = blockIdx.x * blockDim.x + threadIdx.x;
    if (i < e) {
        int d = dst[i];
        int p = atomicAdd(&g_cur[d], 1);
        g_adj[g_row[d] + p] = src[i];
    }
}

// ---------------- tensor-core GEMM (split-bf16, 3-pass) ----------------
__device__ __forceinline__ unsigned pack2(float lo_e, float hi_e) {
    __nv_bfloat162 t = __floats2bfloat162_rn(lo_e, hi_e);   // .x = lo_e (low half)
    return *reinterpret_cast<unsigned*>(&t);
}
__device__ __forceinline__ float bfr(float x) {
    return __bfloat162float(__float2bfloat16_rn(x));
}
__device__ __forceinline__ void mma16816(float* c, const unsigned* a, const unsigned* b) {
    asm volatile(
        "mma.sync.aligned.m16n8k16.row.col.f32.bf16.bf16.f32 "
        "{%0,%1,%2,%3}, {%4,%5,%6,%7}, {%8,%9}, {%0,%1,%2,%3};"
        : "+f"(c[0]), "+f"(c[1]), "+f"(c[2]), "+f"(c[3])
        : "r"(a[0]), "r"(a[1]), "r"(a[2]), "r"(a[3]), "r"(b[0]), "r"(b[1]));
}

// C[M,HID] = act(A)[M,K] @ B[K,HID]; act = BN(scale,shift)+ReLU if scale != null.
__global__ void __launch_bounds__(256, 1) k_gemm_tc(
    const float* __restrict__ A, const float* __restrict__ B,
    float* __restrict__ C, int M, int K,
    const float* __restrict__ scale, const float* __restrict__ shift)
{
    __shared__ unsigned Ahi[128][9], Alo[128][9], Bhi[128][9], Blo[128][9];
    const int tid  = threadIdx.x;
    const int warp = tid >> 5, lane = tid & 31;
    const int grp  = lane >> 2, tig = lane & 3;
    const int bm0  = blockIdx.y * 128;
    const int bn0  = blockIdx.x * 128;

    const int arow = tid >> 1;
    const int akq  = (tid & 1) * 8;
    const int gArow = bm0 + arow;
    const bool aval = (gArow < M);

    const int bn4 = lane * 4;       // 0..124 (n within tile)
    const int bkp = warp;           // 0..7 (k-pair within chunk)

    const int wm0 = (warp >> 2) * 64;
    const int wn0 = (warp & 3) * 32;

    float c[16][4];
    #pragma unroll
    for (int i = 0; i < 16; i++)
        #pragma unroll
        for (int j = 0; j < 4; j++) c[i][j] = 0.f;

    float ar[8];
    float br0[4], br1[4];
    const int KT = K >> 4;

    auto loadG = [&](int kt) {
        // A: 8 consecutive k for one row
        int ka = kt * 16 + akq;
        if (aval) {
            float4 p = *(const float4*)(A + (size_t)gArow * K + ka);
            float4 q = *(const float4*)(A + (size_t)gArow * K + ka + 4);
            ar[0]=p.x; ar[1]=p.y; ar[2]=p.z; ar[3]=p.w;
            ar[4]=q.x; ar[5]=q.y; ar[6]=q.z; ar[7]=q.w;
            if (scale) {
                float4 s  = *(const float4*)(scale + ka);
                float4 s2 = *(const float4*)(scale + ka + 4);
                float4 t  = *(const float4*)(shift + ka);
                float4 t2 = *(const float4*)(shift + ka + 4);
                ar[0]=fmaxf(fmaf(ar[0],s.x, t.x ),0.f); ar[1]=fmaxf(fmaf(ar[1],s.y, t.y ),0.f);
                ar[2]=fmaxf(fmaf(ar[2],s.z, t.z ),0.f); ar[3]=fmaxf(fmaf(ar[3],s.w, t.w ),0.f);
                ar[4]=fmaxf(fmaf(ar[4],s2.x,t2.x),0.f); ar[5]=fmaxf(fmaf(ar[5],s2.y,t2.y),0.f);
                ar[6]=fmaxf(fmaf(ar[6],s2.z,t2.z),0.f); ar[7]=fmaxf(fmaf(ar[7],s2.w,t2.w),0.f);
            }
        } else {
            #pragma unroll
            for (int j = 0; j < 8; j++) ar[j] = 0.f;
        }
        // B: two adjacent k rows, 4 consecutive n
        int kb = kt * 16 + bkp * 2;
        const float* bp = B + (size_t)kb * HID + bn0 + bn4;
        float4 r0 = *(const float4*)bp;
        float4 r1 = *(const float4*)(bp + HID);
        br0[0]=r0.x; br0[1]=r0.y; br0[2]=r0.z; br0[3]=r0.w;
        br1[0]=r1.x; br1[1]=r1.y; br1[2]=r1.z; br1[3]=r1.w;
    };

    auto storeS = [&]() {
        #pragma unroll
        for (int j = 0; j < 8; j += 2) {
            float h0 = bfr(ar[j]), h1 = bfr(ar[j+1]);
            int kp = (akq + j) >> 1;
            Ahi[arow][kp] = pack2(ar[j], ar[j+1]);
            Alo[arow][kp] = pack2(ar[j] - h0, ar[j+1] - h1);
        }
        #pragma unroll
        for (int j = 0; j < 4; j++) {
            float h0 = bfr(br0[j]), h1 = bfr(br1[j]);
            Bhi[bn4 + j][bkp] = pack2(br0[j], br1[j]);
            Blo[bn4 + j][bkp] = pack2(br0[j] - h0, br1[j] - h1);
        }
    };

    loadG(0);
    for (int kt = 0; kt < KT; kt++) {
        storeS();
        __syncthreads();
        if (kt + 1 < KT) loadG(kt + 1);

        unsigned ah[4][4], al[4][4], bh[4][2], bl[4][2];
        #pragma unroll
        for (int mf = 0; mf < 4; mf++) {
            int r = wm0 + mf * 16 + grp;
            ah[mf][0] = Ahi[r][tig];       al[mf][0] = Alo[r][tig];
            ah[mf][1] = Ahi[r + 8][tig];   al[mf][1] = Alo[r + 8][tig];
            ah[mf][2] = Ahi[r][tig + 4];   al[mf][2] = Alo[r][tig + 4];
            ah[mf][3] = Ahi[r + 8][tig+4]; al[mf][3] = Alo[r + 8][tig + 4];
        }
        #pragma unroll
        for (int nf = 0; nf < 4; nf++) {
            int nn = wn0 + nf * 8 + grp;
            bh[nf][0] = Bhi[nn][tig]; bh[nf][1] = Bhi[nn][tig + 4];
            bl[nf][0] = Blo[nn][tig]; bl[nf][1] = Blo[nn][tig + 4];
        }
        #pragma unroll
        for (int mf = 0; mf < 4; mf++)
            #pragma unroll
            for (int nf = 0; nf < 4; nf++) {
                float* cc = c[mf * 4 + nf];
                mma16816(cc, ah[mf], bh[nf]);
                mma16816(cc, ah[mf], bl[nf]);
                mma16816(cc, al[mf], bh[nf]);
            }
        __syncthreads();
    }

    #pragma unroll
    for (int mf = 0; mf < 4; mf++)
        #pragma unroll
        for (int nf = 0; nf < 4; nf++) {
            const float* cc = c[mf * 4 + nf];
            int r0 = bm0 + wm0 + mf * 16 + grp;
            int cn = bn0 + wn0 + nf * 8 + tig * 2;
            if (r0 < M)
                *(float2*)(C + (size_t)r0 * HID + cn) = make_float2(cc[0], cc[1]);
            if (r0 + 8 < M)
                *(float2*)(C + (size_t)(r0 + 8) * HID + cn) = make_float2(cc[2], cc[3]);
        }
}

// ---------------- fused CSR gather + self-loop + bias + BN stats ----------
__global__ void __launch_bounds__(256) k_gather(const float* __restrict__ bias, int n) {
    __shared__ float sh_sum[HID];
    __shared__ float sh_sq[HID];
    const int tid  = threadIdx.x;
    const int lane = tid & 31;
    const int warp = tid >> 5;

    for (int c = tid; c < HID; c += 256) { sh_sum[c] = 0.f; sh_sq[c] = 0.f; }
    __syncthreads();

    const float4 b0 = *(const float4*)(bias + lane * 4);
    const float4 b1 = *(const float4*)(bias + 128 + lane * 4);

    float4 ts0 = make_float4(0,0,0,0), ts1 = make_float4(0,0,0,0);
    float4 tq0 = make_float4(0,0,0,0), tq1 = make_float4(0,0,0,0);

    for (int node = blockIdx.x * 8 + warp; node < n; node += gridDim.x * 8) {
        const int start = g_row[node];
        const int end   = g_row[node + 1];
        const float dd  = g_dinv[node];

        float4 a0 = make_float4(0,0,0,0), a1 = make_float4(0,0,0,0);

        int j = start;
        for (; j + 1 < end; j += 2) {
            int s0 = g_adj[j];
            int s1 = g_adj[j + 1];
            float c0 = g_dinv[s0] * dd;
            float c1 = g_dinv[s1] * dd;
            const float4* p0 = (const float4*)(g_h + (size_t)s0 * HID);
            const float4* p1 = (const float4*)(g_h + (size_t)s1 * HID);
            float4 u0 = p0[lane], u1 = p0[lane + 32];
            float4 w0 = p1[lane], w1 = p1[lane + 32];
            a0.x = fmaf(u0.x, c0, a0.x); a0.y = fmaf(u0.y, c0, a0.y);
            a0.z = fmaf(u0.z, c0, a0.z); a0.w = fmaf(u0.w, c0, a0.w);
            a1.x = fmaf(u1.x, c0, a1.x); a1.y = fmaf(u1.y, c0, a1.y);
            a1.z = fmaf(u1.z, c0, a1.z); a1.w = fmaf(u1.w, c0, a1.w);
            a0.x = fmaf(w0.x, c1, a0.x); a0.y = fmaf(w0.y, c1, a0.y);
            a0.z = fmaf(w0.z, c1, a0.z); a0.w = fmaf(w0.w, c1, a0.w);
            a1.x = fmaf(w1.x, c1, a1.x); a1.y = fmaf(w1.y, c1, a1.y);
            a1.z = fmaf(w1.z, c1, a1.z); a1.w = fmaf(w1.w, c1, a1.w);
        }
        if (j < end) {
            int s0 = g_adj[j];
            float c0 = g_dinv[s0] * dd;
            const float4* p0 = (const float4*)(g_h + (size_t)s0 * HID);
            float4 u0 = p0[lane], u1 = p0[lane + 32];
            a0.x = fmaf(u0.x, c0, a0.x); a0.y = fmaf(u0.y, c0, a0.y);
            a0.z = fmaf(u0.z, c0, a0.z); a0.w = fmaf(u0.w, c0, a0.w);
            a1.x = fmaf(u1.x, c0, a1.x); a1.y = fmaf(u1.y, c0, a1.y);
            a1.z = fmaf(u1.z, c0, a1.z); a1.w = fmaf(u1.w, c0, a1.w);
        }

        const float id = g_invdeg[node];
        const float4* hp = (const float4*)(g_h + (size_t)node * HID);
        float4 h0 = hp[lane], h1 = hp[lane + 32];
        a0.x = fmaf(h0.x, id, a0.x) + b0.x; a0.y = fmaf(h0.y, id, a0.y) + b0.y;
        a0.z = fmaf(h0.z, id, a0.z) + b0.z; a0.w = fmaf(h0.w, id, a0.w) + b0.w;
        a1.x = fmaf(h1.x, id, a1.x) + b1.x; a1.y = fmaf(h1.y, id, a1.y) + b1.y;
        a1.z = fmaf(h1.z, id, a1.z) + b1.z; a1.w = fmaf(h1.w, id, a1.w) + b1.w;

        float4* vp = (float4*)(g_v + (size_t)node * HID);
        vp[lane] = a0;
        vp[lane + 32] = a1;

        ts0.x += a0.x; ts0.y += a0.y; ts0.z += a0.z; ts0.w += a0.w;
        ts1.x += a1.x; ts1.y += a1.y; ts1.z += a1.z; ts1.w += a1.w;
        tq0.x = fmaf(a0.x, a0.x, tq0.x); tq0.y = fmaf(a0.y, a0.y, tq0.y);
        tq0.z = fmaf(a0.z, a0.z, tq0.z); tq0.w = fmaf(a0.w, a0.w, tq0.w);
        tq1.x = fmaf(a1.x, a1.x, tq1.x); tq1.y = fmaf(a1.y, a1.y, tq1.y);
        tq1.z = fmaf(a1.z, a1.z, tq1.z); tq1.w = fmaf(a1.w, a1.w, tq1.w);
    }

    const int c0i = lane * 4;
    atomicAdd(&sh_sum[c0i + 0], ts0.x); atomicAdd(&sh_sum[c0i + 1], ts0.y);
    atomicAdd(&sh_sum[c0i + 2], ts0.z); atomicAdd(&sh_sum[c0i + 3], ts0.w);
    atomicAdd(&sh_sum[c0i + 128], ts1.x); atomicAdd(&sh_sum[c0i + 129], ts1.y);
    atomicAdd(&sh_sum[c0i + 130], ts1.z); atomicAdd(&sh_sum[c0i + 131], ts1.w);
    atomicAdd(&sh_sq[c0i + 0], tq0.x); atomicAdd(&sh_sq[c0i + 1], tq0.y);
    atomicAdd(&sh_sq[c0i + 2], tq0.z); atomicAdd(&sh_sq[c0i + 3], tq0.w);
    atomicAdd(&sh_sq[c0i + 128], tq1.x); atomicAdd(&sh_sq[c0i + 129], tq1.y);
    atomicAdd(&sh_sq[c0i + 130], tq1.z); atomicAdd(&sh_sq[c0i + 131], tq1.w);
    __syncthreads();

    if (tid < HID) {
        atomicAdd(&g_stats[tid], sh_sum[tid]);
        atomicAdd(&g_stats[HID + tid], sh_sq[tid]);
    }
}

// ---------------- fold stats -> scale/shift ----------------
__global__ void k_bn_params(const float* __restrict__ gamma,
                            const float* __restrict__ beta, int n) {
    int c = threadIdx.x;
    float invn = 1.0f / (float)n;
    float mu  = g_stats[c] * invn;
    float var = g_stats[HID + c] * invn - mu * mu;
    var = fmaxf(var, 0.0f);
    float inv = rsqrtf(var + BN_EPS);
    float sc = gamma[c] * inv;
    g_scale[c] = sc;
    g_shift[c] = beta[c] - mu * sc;
}

// ---------------- apply BN + ReLU (final output) ----------------
__global__ void k_apply(float* __restrict__ out, int n) {
    int i = blockIdx.x * blockDim.x + threadIdx.x;
    if (i < n * HID) {
        int c = i & (HID - 1);
        out[i] = fmaxf(fmaf(g_v[i], g_scale[c], g_shift[c]), 0.0f);
    }
}

// ---------------- launch ----------------
extern "C" void kernel_launch(void* const* d_in, const int* in_sizes, int n_in,
                              void* d_out, int out_size) {
    const float* x   = (const float*)d_in[0];
    const int*   ei  = (const int*)  d_in[1];
    const float* W1  = (const float*)d_in[2];
    const float* b1  = (const float*)d_in[3];
    const float* g1  = (const float*)d_in[4];
    const float* be1 = (const float*)d_in[5];
    const float* W2  = (const float*)d_in[6];
    const float* b2  = (const float*)d_in[7];
    const float* g2  = (const float*)d_in[8];
    const float* be2 = (const float*)d_in[9];

    int n = in_sizes[0] / 384;
    int e = in_sizes[1] / 2;
    const int* src = ei;
    const int* dst = ei + e;

    void *p_h = nullptr, *p_v = nullptr, *p_stats = nullptr;
    void *p_cnt = nullptr, *p_cur = nullptr, *p_scale = nullptr, *p_shift = nullptr;
    cudaGetSymbolAddress(&p_h,     g_h);
    cudaGetSymbolAddress(&p_v,     g_v);
    cudaGetSymbolAddress(&p_stats, g_stats);
    cudaGetSymbolAddress(&p_cnt,   g_cnt);
    cudaGetSymbolAddress(&p_cur,   g_cur);
    cudaGetSymbolAddress(&p_scale, g_scale);
    cudaGetSymbolAddress(&p_shift, g_shift);

    const int T = 256;
    dim3 ggrid(HID / 128, (n + 127) / 128);
    const int gat_grid = 1184;
    int agrid = (int)(((long)n * HID + T - 1) / T);

    // ---- CSR build ----
    cudaMemsetAsync(p_cnt, 0, (size_t)n * sizeof(int));
    cudaMemsetAsync(p_cur, 0, (size_t)n * sizeof(int));
    k_count<<<(e + T - 1) / T, T>>>(dst, e);
    k_dinv<<<(n + T - 1) / T, T>>>(n);
    k_scan<<<1, 1024>>>(n);
    k_fill<<<(e + T - 1) / T, T>>>(src, dst, e);

    // ---- layer 1 ----
    cudaMemsetAsync(p_stats, 0, 2 * HID * sizeof(float));
    k_gemm_tc<<<ggrid, 256>>>(x, W1, (float*)p_h, n, 384, nullptr, nullptr);
    k_gather<<<gat_grid, 256>>>(b1, n);
    k_bn_params<<<1, HID>>>(g1, be1, n);

    // ---- layer 2 (BN1+ReLU fused into A-load) ----
    cudaMemsetAsync(p_stats, 0, 2 * HID * sizeof(float));
    k_gemm_tc<<<ggrid, 256>>>((const float*)p_v, W2, (float*)p_h, n, 256,
                              (const float*)p_scale, (const float*)p_shift);
    k_gather<<<gat_grid, 256>>>(b2, n);
    k_bn_params<<<1, HID>>>(g2, be2, n);
    k_apply<<<agrid, T>>>((float*)d_out, n);
}

// round 8
// speedup vs baseline: 2.2165x; 1.1106x over previous
#include <cuda_runtime.h>
#include <cuda_bf16.h>
#include <math.h>
#include <stdint.h>

#define MAXN 100000
#define MAXE 800000
#define HID 256
#define BN_EPS 1e-5f

// ---------------- scratch (device globals) ----------------
__device__ float g_h[(size_t)MAXN * HID];      // GEMM output
__device__ float g_v[(size_t)MAXN * HID];      // gathered pre-BN activations
__device__ float g_dinv[MAXN];
__device__ float g_invdeg[MAXN];
__device__ int   g_cnt[MAXN];
__device__ int   g_cur[MAXN];
__device__ int   g_row[MAXN + 1];
__device__ int   g_adj[MAXE];
__device__ float g_stats[2 * HID];
__device__ float g_scale[HID];
__device__ float g_shift[HID];

// ---------------- CSR build ----------------
__global__ void k_count(const int* __restrict__ dst, int e) {
    int i = blockIdx.x * blockDim.x + threadIdx.x;
    if (i < e) atomicAdd(&g_cnt[dst[i]], 1);
}

__global__ void k_dinv(int n) {
    int i = blockIdx.x * blockDim.x + threadIdx.x;
    if (i < n) {
        float d = (float)g_cnt[i] + 1.0f;
        g_dinv[i] = rsqrtf(d);
        g_invdeg[i] = 1.0f / d;
    }
}

__global__ void __launch_bounds__(1024) k_scan(int n) {
    __shared__ int sh[1024];
    const int t = threadIdx.x;
    const int chunk = (n + 1023) >> 10;
    int lo = t * chunk;
    int hi = lo + chunk; if (hi > n) hi = n; if (lo > n) lo = n;
    int s = 0;
    for (int i = lo; i < hi; i++) s += g_cnt[i];
    sh[t] = s;
    __syncthreads();
    for (int off = 1; off < 1024; off <<= 1) {
        int v = (t >= off) ? sh[t - off] : 0;
        __syncthreads();
        sh[t] += v;
        __syncthreads();
    }
    int run = (t == 0) ? 0 : sh[t - 1];
    for (int i = lo; i < hi; i++) {
        g_row[i] = run;
        run += g_cnt[i];
    }
    if (hi == n) g_row[n] = run;
}

__global__ void k_fill(const int* __restrict__ src, const int* __restrict__ dst, int e) {
    int i = blockIdx.x * blockDim.x + threadIdx.x;
    if (i < e) {
        int d = dst[i];
        int p = atomicAdd(&g_cur[d], 1);
        g_adj[g_row[d] + p] = src[i];
    }
}

// ---------------- tensor-core GEMM (split-bf16, mma.sync, pipelined) -------
__device__ __forceinline__ unsigned pack2(float a, float b) {
    __nv_bfloat162 t = __floats2bfloat162_rn(a, b);   // .x = a (low half)
    return *reinterpret_cast<unsigned*>(&t);
}
__device__ __forceinline__ float bfr(float x) {
    return __bfloat162float(__float2bfloat16_rn(x));
}
__device__ __forceinline__ void mma16816(float* c, const unsigned* a, const unsigned* b) {
    asm volatile(
        "mma.sync.aligned.m16n8k16.row.col.f32.bf16.bf16.f32 "
        "{%0,%1,%2,%3}, {%4,%5,%6,%7}, {%8,%9}, {%0,%1,%2,%3};"
        : "+f"(c[0]), "+f"(c[1]), "+f"(c[2]), "+f"(c[3])
        : "r"(a[0]), "r"(a[1]), "r"(a[2]), "r"(a[3]), "r"(b[0]), "r"(b[1]));
}

#define PAD 9
// C[M,HID] = act(A)[M,K] @ W[K,HID]; act = BN(scale,shift)+ReLU if scale != null.
// Block tile 128x128, K-stage 16, 512 threads (16 warps at 32x32), double-buffered.
__global__ void __launch_bounds__(512, 1) k_gemm(
    const float* __restrict__ A, const float* __restrict__ W,
    float* __restrict__ C, int M, int K,
    const float* __restrict__ scale, const float* __restrict__ shift)
{
    __shared__ unsigned Ahi[2][128 * PAD], Alo[2][128 * PAD];
    __shared__ unsigned Bhi[2][128 * PAD], Blo[2][128 * PAD];

    const int tid  = threadIdx.x;
    const int warp = tid >> 5, lane = tid & 31;
    const int grp  = lane >> 2, tig = lane & 3;
    const int bm0  = blockIdx.y * 128;
    const int bn0  = blockIdx.x * 128;

    const int wm0 = (warp >> 2) * 32;
    const int wn0 = (warp & 3) * 32;

    // A staging: row = tid>>2 (0..127), kq = (tid&3)*4
    const int arow = tid >> 2;
    const int akq  = (tid & 3) * 4;
    const int gArow = bm0 + arow;
    const bool aval = gArow < M;

    // B staging: n2 = tid&63 (n pair), kp = tid>>6 (0..7)
    const int bn2 = (tid & 63) * 2;
    const int bkp = tid >> 6;

    float c[8][4];
    #pragma unroll
    for (int i = 0; i < 8; i++)
        #pragma unroll
        for (int j = 0; j < 4; j++) c[i][j] = 0.f;

    float ar[4];
    float b0x, b0y, b1x, b1y;
    const int KT = K >> 4;

    auto loadG = [&](int kt) {
        const int ka = kt * 16 + akq;
        if (aval) {
            float4 v = *(const float4*)(A + (size_t)gArow * K + ka);
            ar[0] = v.x; ar[1] = v.y; ar[2] = v.z; ar[3] = v.w;
            if (scale) {
                float4 s = *(const float4*)(scale + ka);
                float4 t = *(const float4*)(shift + ka);
                ar[0] = fmaxf(fmaf(ar[0], s.x, t.x), 0.f);
                ar[1] = fmaxf(fmaf(ar[1], s.y, t.y), 0.f);
                ar[2] = fmaxf(fmaf(ar[2], s.z, t.z), 0.f);
                ar[3] = fmaxf(fmaf(ar[3], s.w, t.w), 0.f);
            }
        } else {
            ar[0] = ar[1] = ar[2] = ar[3] = 0.f;
        }
        const int kb = kt * 16 + bkp * 2;
        const float* bp = W + (size_t)kb * HID + bn0 + bn2;
        float2 r0 = *(const float2*)bp;
        float2 r1 = *(const float2*)(bp + HID);
        b0x = r0.x; b0y = r0.y; b1x = r1.x; b1y = r1.y;
    };

    auto storeS = [&](int s) {
        const int kp0 = akq >> 1;
        Ahi[s][arow * PAD + kp0]     = pack2(ar[0], ar[1]);
        Ahi[s][arow * PAD + kp0 + 1] = pack2(ar[2], ar[3]);
        Alo[s][arow * PAD + kp0]     = pack2(ar[0] - bfr(ar[0]), ar[1] - bfr(ar[1]));
        Alo[s][arow * PAD + kp0 + 1] = pack2(ar[2] - bfr(ar[2]), ar[3] - bfr(ar[3]));
        Bhi[s][bn2 * PAD + bkp]       = pack2(b0x, b1x);
        Bhi[s][(bn2 + 1) * PAD + bkp] = pack2(b0y, b1y);
        Blo[s][bn2 * PAD + bkp]       = pack2(b0x - bfr(b0x), b1x - bfr(b1x));
        Blo[s][(bn2 + 1) * PAD + bkp] = pack2(b0y - bfr(b0y), b1y - bfr(b1y));
    };

    loadG(0);
    storeS(0);
    __syncthreads();

    for (int kt = 0; kt < KT; kt++) {
        const int s = kt & 1;
        const bool more = kt + 1 < KT;
        if (more) loadG(kt + 1);

        unsigned ah[2][4], al[2][4], bh[4][2], bl[4][2];
        #pragma unroll
        for (int mf = 0; mf < 2; mf++) {
            const int r = wm0 + mf * 16 + grp;
            ah[mf][0] = Ahi[s][r * PAD + tig];
            ah[mf][1] = Ahi[s][(r + 8) * PAD + tig];
            ah[mf][2] = Ahi[s][r * PAD + tig + 4];
            ah[mf][3] = Ahi[s][(r + 8) * PAD + tig + 4];
            al[mf][0] = Alo[s][r * PAD + tig];
            al[mf][1] = Alo[s][(r + 8) * PAD + tig];
            al[mf][2] = Alo[s][r * PAD + tig + 4];
            al[mf][3] = Alo[s][(r + 8) * PAD + tig + 4];
        }
        #pragma unroll
        for (int nf = 0; nf < 4; nf++) {
            const int nn = wn0 + nf * 8 + grp;
            bh[nf][0] = Bhi[s][nn * PAD + tig];
            bh[nf][1] = Bhi[s][nn * PAD + tig + 4];
            bl[nf][0] = Blo[s][nn * PAD + tig];
            bl[nf][1] = Blo[s][nn * PAD + tig + 4];
        }

        if (more) storeS(s ^ 1);

        #pragma unroll
        for (int mf = 0; mf < 2; mf++)
            #pragma unroll
            for (int nf = 0; nf < 4; nf++) {
                float* cc = c[mf * 4 + nf];
                mma16816(cc, ah[mf], bh[nf]);
                mma16816(cc, ah[mf], bl[nf]);
                mma16816(cc, al[mf], bh[nf]);
            }
        if (more) __syncthreads();
    }

    #pragma unroll
    for (int mf = 0; mf < 2; mf++)
        #pragma unroll
        for (int nf = 0; nf < 4; nf++) {
            const float* cc = c[mf * 4 + nf];
            const int r0 = bm0 + wm0 + mf * 16 + grp;
            const int cn = bn0 + wn0 + nf * 8 + tig * 2;
            if (r0 < M)
                *(float2*)(C + (size_t)r0 * HID + cn) = make_float2(cc[0], cc[1]);
            if (r0 + 8 < M)
                *(float2*)(C + (size_t)(r0 + 8) * HID + cn) = make_float2(cc[2], cc[3]);
        }
}

// ---------------- fused CSR gather + self-loop + bias + BN stats ----------
__global__ void __launch_bounds__(256) k_gather(const float* __restrict__ bias, int n) {
    __shared__ float sh_sum[HID];
    __shared__ float sh_sq[HID];
    const int tid  = threadIdx.x;
    const int lane = tid & 31;
    const int warp = tid >> 5;

    for (int c = tid; c < HID; c += 256) { sh_sum[c] = 0.f; sh_sq[c] = 0.f; }
    __syncthreads();

    const float4 b0 = *(const float4*)(bias + lane * 4);
    const float4 b1 = *(const float4*)(bias + 128 + lane * 4);

    float4 ts0 = make_float4(0,0,0,0), ts1 = make_float4(0,0,0,0);
    float4 tq0 = make_float4(0,0,0,0), tq1 = make_float4(0,0,0,0);

    for (int node = blockIdx.x * 8 + warp; node < n; node += gridDim.x * 8) {
        const int start = g_row[node];
        const int end   = g_row[node + 1];
        const float dd  = g_dinv[node];

        float4 a0 = make_float4(0,0,0,0), a1 = make_float4(0,0,0,0);

        int j = start;
        for (; j + 1 < end; j += 2) {
            int s0 = g_adj[j];
            int s1 = g_adj[j + 1];
            float c0 = g_dinv[s0] * dd;
            float c1 = g_dinv[s1] * dd;
            const float4* p0 = (const float4*)(g_h + (size_t)s0 * HID);
            const float4* p1 = (const float4*)(g_h + (size_t)s1 * HID);
            float4 u0 = p0[lane], u1 = p0[lane + 32];
            float4 w0 = p1[lane], w1 = p1[lane + 32];
            a0.x = fmaf(u0.x, c0, a0.x); a0.y = fmaf(u0.y, c0, a0.y);
            a0.z = fmaf(u0.z, c0, a0.z); a0.w = fmaf(u0.w, c0, a0.w);
            a1.x = fmaf(u1.x, c0, a1.x); a1.y = fmaf(u1.y, c0, a1.y);
            a1.z = fmaf(u1.z, c0, a1.z); a1.w = fmaf(u1.w, c0, a1.w);
            a0.x = fmaf(w0.x, c1, a0.x); a0.y = fmaf(w0.y, c1, a0.y);
            a0.z = fmaf(w0.z, c1, a0.z); a0.w = fmaf(w0.w, c1, a0.w);
            a1.x = fmaf(w1.x, c1, a1.x); a1.y = fmaf(w1.y, c1, a1.y);
            a1.z = fmaf(w1.z, c1, a1.z); a1.w = fmaf(w1.w, c1, a1.w);
        }
        if (j < end) {
            int s0 = g_adj[j];
            float c0 = g_dinv[s0] * dd;
            const float4* p0 = (const float4*)(g_h + (size_t)s0 * HID);
            float4 u0 = p0[lane], u1 = p0[lane + 32];
            a0.x = fmaf(u0.x, c0, a0.x); a0.y = fmaf(u0.y, c0, a0.y);
            a0.z = fmaf(u0.z, c0, a0.z); a0.w = fmaf(u0.w, c0, a0.w);
            a1.x = fmaf(u1.x, c0, a1.x); a1.y = fmaf(u1.y, c0, a1.y);
            a1.z = fmaf(u1.z, c0, a1.z); a1.w = fmaf(u1.w, c0, a1.w);
        }

        const float id = g_invdeg[node];
        const float4* hp = (const float4*)(g_h + (size_t)node * HID);
        float4 h0 = hp[lane], h1 = hp[lane + 32];
        a0.x = fmaf(h0.x, id, a0.x) + b0.x; a0.y = fmaf(h0.y, id, a0.y) + b0.y;
        a0.z = fmaf(h0.z, id, a0.z) + b0.z; a0.w = fmaf(h0.w, id, a0.w) + b0.w;
        a1.x = fmaf(h1.x, id, a1.x) + b1.x; a1.y = fmaf(h1.y, id, a1.y) + b1.y;
        a1.z = fmaf(h1.z, id, a1.z) + b1.z; a1.w = fmaf(h1.w, id, a1.w) + b1.w;

        float4* vp = (float4*)(g_v + (size_t)node * HID);
        vp[lane] = a0;
        vp[lane + 32] = a1;

        ts0.x += a0.x; ts0.y += a0.y; ts0.z += a0.z; ts0.w += a0.w;
        ts1.x += a1.x; ts1.y += a1.y; ts1.z += a1.z; ts1.w += a1.w;
        tq0.x = fmaf(a0.x, a0.x, tq0.x); tq0.y = fmaf(a0.y, a0.y, tq0.y);
        tq0.z = fmaf(a0.z, a0.z, tq0.z); tq0.w = fmaf(a0.w, a0.w, tq0.w);
        tq1.x = fmaf(a1.x, a1.x, tq1.x); tq1.y = fmaf(a1.y, a1.y, tq1.y);
        tq1.z = fmaf(a1.z, a1.z, tq1.z); tq1.w = fmaf(a1.w, a1.w, tq1.w);
    }

    const int c0i = lane * 4;
    atomicAdd(&sh_sum[c0i + 0], ts0.x); atomicAdd(&sh_sum[c0i + 1], ts0.y);
    atomicAdd(&sh_sum[c0i + 2], ts0.z); atomicAdd(&sh_sum[c0i + 3], ts0.w);
    atomicAdd(&sh_sum[c0i + 128], ts1.x); atomicAdd(&sh_sum[c0i + 129], ts1.y);
    atomicAdd(&sh_sum[c0i + 130], ts1.z); atomicAdd(&sh_sum[c0i + 131], ts1.w);
    atomicAdd(&sh_sq[c0i + 0], tq0.x); atomicAdd(&sh_sq[c0i + 1], tq0.y);
    atomicAdd(&sh_sq[c0i + 2], tq0.z); atomicAdd(&sh_sq[c0i + 3], tq0.w);
    atomicAdd(&sh_sq[c0i + 128], tq1.x); atomicAdd(&sh_sq[c0i + 129], tq1.y);
    atomicAdd(&sh_sq[c0i + 130], tq1.z); atomicAdd(&sh_sq[c0i + 131], tq1.w);
    __syncthreads();

    if (tid < HID) {
        atomicAdd(&g_stats[tid], sh_sum[tid]);
        atomicAdd(&g_stats[HID + tid], sh_sq[tid]);
    }
}

// ---------------- fold stats -> scale/shift ----------------
__global__ void k_bn_params(const float* __restrict__ gamma,
                            const float* __restrict__ beta, int n) {
    int c = threadIdx.x;
    float invn = 1.0f / (float)n;
    float mu  = g_stats[c] * invn;
    float var = g_stats[HID + c] * invn - mu * mu;
    var = fmaxf(var, 0.0f);
    float inv = rsqrtf(var + BN_EPS);
    float sc = gamma[c] * inv;
    g_scale[c] = sc;
    g_shift[c] = beta[c] - mu * sc;
}

// ---------------- apply BN + ReLU (final output) ----------------
__global__ void k_apply(float* __restrict__ out, int n) {
    int i = blockIdx.x * blockDim.x + threadIdx.x;
    if (i < n * HID) {
        int c = i & (HID - 1);
        out[i] = fmaxf(fmaf(g_v[i], g_scale[c], g_shift[c]), 0.0f);
    }
}

// ---------------- launch ----------------
extern "C" void kernel_launch(void* const* d_in, const int* in_sizes, int n_in,
                              void* d_out, int out_size) {
    const float* x   = (const float*)d_in[0];
    const int*   ei  = (const int*)  d_in[1];
    const float* W1  = (const float*)d_in[2];
    const float* b1  = (const float*)d_in[3];
    const float* g1  = (const float*)d_in[4];
    const float* be1 = (const float*)d_in[5];
    const float* W2  = (const float*)d_in[6];
    const float* b2  = (const float*)d_in[7];
    const float* g2  = (const float*)d_in[8];
    const float* be2 = (const float*)d_in[9];

    int n = in_sizes[0] / 384;
    int e = in_sizes[1] / 2;
    const int* src = ei;
    const int* dst = ei + e;

    void *p_h = nullptr, *p_v = nullptr, *p_stats = nullptr;
    void *p_cnt = nullptr, *p_cur = nullptr, *p_scale = nullptr, *p_shift = nullptr;
    cudaGetSymbolAddress(&p_h,     g_h);
    cudaGetSymbolAddress(&p_v,     g_v);
    cudaGetSymbolAddress(&p_stats, g_stats);
    cudaGetSymbolAddress(&p_cnt,   g_cnt);
    cudaGetSymbolAddress(&p_cur,   g_cur);
    cudaGetSymbolAddress(&p_scale, g_scale);
    cudaGetSymbolAddress(&p_shift, g_shift);

    const int T = 256;
    dim3 ggrid(HID / 128, (n + 127) / 128);
    const int gat_grid = 1184;
    int agrid = (int)(((long)n * HID + T - 1) / T);

    // launch order puts k_gemm (layer 1) 6th so ncu -s 5 -c 1 profiles it.
    cudaMemsetAsync(p_cnt, 0, (size_t)n * sizeof(int));            // 1
    cudaMemsetAsync(p_cur, 0, (size_t)n * sizeof(int));            // 2
    cudaMemsetAsync(p_stats, 0, 2 * HID * sizeof(float));          // 3
    k_count<<<(e + T - 1) / T, T>>>(dst, e);                       // 4
    k_dinv<<<(n + T - 1) / T, T>>>(n);                             // 5
    k_gemm<<<ggrid, 512>>>(x, W1, (float*)p_h, n, 384, nullptr, nullptr);  // 6
    k_scan<<<1, 1024>>>(n);                                        // 7
    k_fill<<<(e + T - 1) / T, T>>>(src, dst, e);                   // 8

    // ---- layer 1 tail ----
    k_gather<<<gat_grid, 256>>>(b1, n);
    k_bn_params<<<1, HID>>>(g1, be1, n);

    // ---- layer 2 (BN1+ReLU fused into A-load) ----
    cudaMemsetAsync(p_stats, 0, 2 * HID * sizeof(float));
    k_gemm<<<ggrid, 512>>>((const float*)p_v, W2, (float*)p_h, n, 256,
                           (const float*)p_scale, (const float*)p_shift);
    k_gather<<<gat_grid, 256>>>(b2, n);
    k_bn_params<<<1, HID>>>(g2, be2, n);
    k_apply<<<agrid, T>>>((float*)d_out, n);
}